// round 1
// baseline (speedup 1.0000x reference)
#include <cuda_runtime.h>

// ---------------------------------------------------------------------------
// FCOS head, fp32 direct conv baseline.
// Layer-by-layer conv3x3 (SAME, stride 1) through ping-pong device scratch.
// Block tile: 64 out-channels x (8x8) pixels, 256 threads, 4x4 regs/thread.
// Cin chunked by 16 through shared memory.
// ---------------------------------------------------------------------------

#define KC    16   // cin chunk
#define TCO   64   // cout tile
#define TSP   8    // spatial tile edge
#define IPAD  13   // s_in col pad (conflict-free: 13*r + {0,4} distinct mod 32)
#define WPAD  68   // s_w co pad (mult of 4 -> float4 aligned)

// 16 * 256 * 64 * 64 floats = 64 MiB each
__device__ float g_bufA[16u * 256u * 64u * 64u];
__device__ float g_bufB[16u * 256u * 64u * 64u];

__global__ __launch_bounds__(256)
void conv3x3_k(const float* __restrict__ in,    // [B][256][H][W], image n used
               const float* __restrict__ wgt,   // [coutValid<split part][256][3][3]
               const float* __restrict__ bias,
               const float* __restrict__ wgt2,  // co >= split part (ctr), may be null
               const float* __restrict__ bias2,
               float* __restrict__ out,
               int H, int W, int coutValid, int split, int relu,
               int outMode, int locOff, int chOff)
{
    __shared__ __align__(16) float s_w[KC][9][WPAD];
    __shared__ float s_in[KC][10][IPAD];

    const int tid    = threadIdx.x;
    const int n      = blockIdx.z;
    const int coBase = blockIdx.y * TCO;
    const int tilesX = W / TSP;
    const int tx0    = (blockIdx.x % tilesX) * TSP;
    const int ty0    = (blockIdx.x / tilesX) * TSP;

    const int pid = tid & 15;          // 16 pixel-quads
    const int cog = tid >> 4;          // 16 co-groups of 4
    const int r   = pid >> 1;          // row in tile 0..7
    const int cq  = (pid & 1) * 4;     // col base 0 or 4

    const float* inN = in + (size_t)n * 256 * H * W;

    float acc[4][4];
#pragma unroll
    for (int i = 0; i < 4; i++)
#pragma unroll
        for (int j = 0; j < 4; j++) acc[i][j] = 0.f;

    for (int c0 = 0; c0 < 256; c0 += KC) {
        __syncthreads();
        // ---- load input patch: KC x 10 x 10 (zero-padded borders) ----
        for (int idx = tid; idx < KC * 100; idx += 256) {
            int ci = idx / 100;
            int rr = (idx / 10) % 10;
            int cc = idx % 10;
            int gy = ty0 - 1 + rr;
            int gx = tx0 - 1 + cc;
            float v = 0.f;
            if (gy >= 0 && gy < H && gx >= 0 && gx < W)
                v = inN[(size_t)(c0 + ci) * H * W + gy * W + gx];
            s_in[ci][rr][cc] = v;
        }
        // ---- load weights (gmem-contiguous order), layout [ci][k][co] ----
        for (int idx = tid; idx < TCO * KC * 9; idx += 256) {
            int co  = idx / (KC * 9);
            int rem = idx % (KC * 9);
            int ci  = rem / 9;
            int k   = rem % 9;
            int gco = coBase + co;
            float v = 0.f;
            if (gco < coutValid) {
                const float* wp = (gco < split)
                    ? wgt  + ((size_t)gco * 256 + (c0 + ci)) * 9 + k
                    : wgt2 + ((size_t)(gco - split) * 256 + (c0 + ci)) * 9 + k;
                v = *wp;
            }
            s_w[ci][k][co] = v;
        }
        __syncthreads();

        // ---- compute ----
#pragma unroll 2
        for (int ci = 0; ci < KC; ci++) {
#pragma unroll
            for (int ky = 0; ky < 3; ky++) {
                float rv[6];
#pragma unroll
                for (int j = 0; j < 6; j++) rv[j] = s_in[ci][r + ky][cq + j];
#pragma unroll
                for (int kx = 0; kx < 3; kx++) {
                    const float4 wv =
                        *(const float4*)&s_w[ci][ky * 3 + kx][cog * 4];
#pragma unroll
                    for (int j = 0; j < 4; j++) {
                        acc[0][j] += wv.x * rv[kx + j];
                        acc[1][j] += wv.y * rv[kx + j];
                        acc[2][j] += wv.z * rv[kx + j];
                        acc[3][j] += wv.w * rv[kx + j];
                    }
                }
            }
        }
    }

    // ---- epilogue ----
#pragma unroll
    for (int i = 0; i < 4; i++) {
        int gco = coBase + cog * 4 + i;
        if (gco >= coutValid) continue;
        float b = (gco < split) ? bias[gco] : bias2[gco - split];
#pragma unroll
        for (int j = 0; j < 4; j++) {
            float v = acc[i][j] + b;
            if (relu) v = fmaxf(v, 0.f);
            int y = ty0 + r, x = tx0 + cq + j;
            if (outMode == 0) {
                out[((size_t)n * 256 + gco) * H * W + y * W + x] = v;
            } else {
                // final output: (B, 5376, 85) channels-last
                out[((size_t)n * 5376 + (locOff + (size_t)y * W + x)) * 85
                    + chOff + gco] = v;
            }
        }
    }
}

extern "C" void kernel_launch(void* const* d_in, const int* in_sizes, int n_in,
                              void* d_out, int out_size)
{
    const float* feat[3] = {(const float*)d_in[0], (const float*)d_in[1],
                            (const float*)d_in[2]};
    const float* scw = (const float*)d_in[3];   // stem_cls_w (4,256,256,3,3)
    const float* scb = (const float*)d_in[4];   // stem_cls_b (4,256)
    const float* sbw = (const float*)d_in[5];   // stem_box_w
    const float* sbb = (const float*)d_in[6];   // stem_box_b
    const float* pcw = (const float*)d_in[7];   // pred_cls_w (80,256,3,3)
    const float* pcb = (const float*)d_in[8];
    const float* pbw = (const float*)d_in[9];   // pred_box_w (4,256,3,3)
    const float* pbb = (const float*)d_in[10];
    const float* pqw = (const float*)d_in[11];  // pred_ctr_w (1,256,3,3)
    const float* pqb = (const float*)d_in[12];
    float* out = (float*)d_out;

    float *bufA, *bufB;
    cudaGetSymbolAddress((void**)&bufA, g_bufA);
    cudaGetSymbolAddress((void**)&bufB, g_bufB);

    const int   Hs[3]  = {64, 32, 16};
    const int   loc[3] = {0, 4096, 5120};
    const size_t wstep = 256 * 256 * 9;

    for (int L = 0; L < 3; L++) {
        int H = Hs[L], W = Hs[L];
        dim3 grid((W / TSP) * (H / TSP), 256 / TCO, 16);
        float* dsts[4] = {bufA, bufB, bufA, bufB};

        // ---- cls stem (4 x conv+relu) ----
        const float* src = feat[L];
        for (int i = 0; i < 4; i++) {
            conv3x3_k<<<grid, 256>>>(src, scw + i * wstep, scb + i * 256,
                                     nullptr, nullptr, dsts[i],
                                     H, W, 256, 256, 1, 0, 0, 0);
            src = dsts[i];
        }
        // ---- pred_cls (80 ch) -> out channels [0,80) ----
        dim3 gridc((W / TSP) * (H / TSP), 2, 16);
        conv3x3_k<<<gridc, 256>>>(src, pcw, pcb, nullptr, nullptr,
                                  out, H, W, 80, 80, 0, 1, loc[L], 0);

        // ---- box stem ----
        src = feat[L];
        for (int i = 0; i < 4; i++) {
            conv3x3_k<<<grid, 256>>>(src, sbw + i * wstep, sbb + i * 256,
                                     nullptr, nullptr, dsts[i],
                                     H, W, 256, 256, 1, 0, 0, 0);
            src = dsts[i];
        }
        // ---- pred_box (4) + pred_ctr (1) -> out channels [80,85) ----
        dim3 gridb((W / TSP) * (H / TSP), 1, 16);
        conv3x3_k<<<gridb, 256>>>(src, pbw, pbb, pqw, pqb,
                                  out, H, W, 5, 4, 0, 1, loc[L], 80);
    }
}